// round 1
// baseline (speedup 1.0000x reference)
#include <cuda_runtime.h>
#include <cuda_bf16.h>

#define NV 8192
#define EPSV 1e-5f
#define MAXSPAN 2048
#define NPART 64
#define PSIZE 128           /* NV / NPART */
#define ECAP (1 << 22)      /* 4M edge slots, ~12x headroom over expected ~335K */

// ---------------- device scratch (allocation-free contract) ----------------
__device__ int      g_deg[NV];
__device__ unsigned g_edges[ECAP];
__device__ int      g_ecount;
__device__ int      g_dmin, g_dmax;
__device__ double   g_sum;
__device__ int      g_hist[NPART * MAXSPAN];
__device__ float    g_Tbase[(size_t)MAXSPAN * MAXSPAN];  // log(1-p+eps) table
__device__ float    g_Tdiff[(size_t)MAXSPAN * MAXSPAN];  // log(p+eps)-log(1-p+eps)

// ---------------- K0: reset per-replay state ----------------
__global__ void k_init() {
    g_ecount = 0;
    g_sum = 0.0;
    g_dmin = 0x7fffffff;
    g_dmax = 0;
}

// ---------------- K1: fused row-degree + upper-tri edge extraction --------
// One block per row; 256 threads x 8 float4 = 8192 floats (full row, coalesced).
// Edge indices compacted via block scan; ONE global atomic per block.
__global__ void __launch_bounds__(256) k_deg_edges(const float* __restrict__ g) {
    int row = blockIdx.x;
    const float4* rp = (const float4*)(g + (size_t)row * NV);
    unsigned mask = 0, umask = 0;
#pragma unroll
    for (int k = 0; k < 8; k++) {
        float4 v = __ldg(&rp[k * 256 + threadIdx.x]);
        int jb = k * 1024 + threadIdx.x * 4;     // column of v.x
        unsigned m = (v.x != 0.f ? 1u : 0u) | (v.y != 0.f ? 2u : 0u) |
                     (v.z != 0.f ? 4u : 0u) | (v.w != 0.f ? 8u : 0u);
        mask |= m << (4 * k);
        unsigned um = m;
        if (jb + 3 < row) {
            um = 0;
        } else if (jb < row) {
            unsigned keep = 0;
#pragma unroll
            for (int c = 0; c < 4; c++)
                if (jb + c >= row) keep |= 1u << c;
            um &= keep;
        }
        umask |= um << (4 * k);
    }
    int degc = __popc(mask);
    int cnt  = __popc(umask);
    int lane = threadIdx.x & 31, wid = threadIdx.x >> 5;

    // warp inclusive scan of edge counts
    int inc = cnt;
#pragma unroll
    for (int o = 1; o < 32; o <<= 1) {
        int nn = __shfl_up_sync(0xffffffffu, inc, o);
        if (lane >= o) inc += nn;
    }
    // warp reduce of degree
    int dsum = degc;
#pragma unroll
    for (int o = 16; o; o >>= 1) dsum += __shfl_down_sync(0xffffffffu, dsum, o);

    __shared__ int wsum[8], wdeg[8], wbase[8], sbase;
    if (lane == 31) wsum[wid] = inc;
    if (lane == 0)  wdeg[wid] = dsum;
    __syncthreads();
    if (threadIdx.x == 0) {
        int run = 0, dt = 0;
        for (int w = 0; w < 8; w++) { wbase[w] = run; run += wsum[w]; dt += wdeg[w]; }
        g_deg[row] = dt;
        sbase = atomicAdd(&g_ecount, run);
    }
    __syncthreads();

    int off = sbase + wbase[wid] + inc - cnt;
    unsigned m2 = umask;
    while (m2) {
        int b = __ffs(m2) - 1; m2 &= m2 - 1;
        int j = (b >> 2) * 1024 + threadIdx.x * 4 + (b & 3);
        if (off < ECAP) g_edges[off] = ((unsigned)row << 13) | (unsigned)j;
        off++;
    }
}

// ---------------- K2: degree min/max ----------------
__global__ void k_minmax() {
    int i = blockIdx.x * blockDim.x + threadIdx.x;
    int v = g_deg[i];
    int mn = v, mx = v;
#pragma unroll
    for (int o = 16; o; o >>= 1) {
        mn = min(mn, __shfl_down_sync(0xffffffffu, mn, o));
        mx = max(mx, __shfl_down_sync(0xffffffffu, mx, o));
    }
    __shared__ int smn[8], smx[8];
    int lane = threadIdx.x & 31, wid = threadIdx.x >> 5;
    if (lane == 0) { smn[wid] = mn; smx[wid] = mx; }
    __syncthreads();
    if (threadIdx.x == 0) {
        int a = smn[0], b = smx[0];
        for (int w = 1; w < 8; w++) { a = min(a, smn[w]); b = max(b, smx[w]); }
        atomicMin(&g_dmin, a);
        atomicMax(&g_dmax, b);
    }
}

// ---------------- K3: fill degree-pair tables (span^2 ~ 12K entries) ------
__global__ void k_fill(const float* __restrict__ params) {
    float alpha = params[0], beta = params[1], sigma = params[2];
    int dmin = g_dmin;
    int span = g_dmax - dmin + 1;
    if (span > MAXSPAN) span = MAXSPAN;
    long total = (long)span * span;
    for (long idx = (long)blockIdx.x * blockDim.x + threadIdx.x; idx < total;
         idx += (long)gridDim.x * blockDim.x) {
        int a = (int)(idx % span);  // i-side bin (alpha)
        int b = (int)(idx / span);  // j-side bin (beta)
        float s = alpha * (float)(dmin + a) + beta * (float)(dmin + b) + sigma;
        float p = 1.f / (1.f + expf(s));
        float l1 = logf(p + EPSV);
        float l0 = logf(1.f - p + EPSV);
        g_Tbase[idx] = l0;
        g_Tdiff[idx] = l1 - l0;
    }
}

// ---------------- K4: per-partition degree histograms ----------------
__global__ void __launch_bounds__(PSIZE) k_hist() {
    __shared__ int h[MAXSPAN];
    int dmin = g_dmin;
    int span = min(g_dmax - dmin + 1, MAXSPAN);
    for (int b = threadIdx.x; b < span; b += blockDim.x) h[b] = 0;
    __syncthreads();
    int i = blockIdx.x * PSIZE + threadIdx.x;
    int b = min(max(g_deg[i] - dmin, 0), span - 1);
    atomicAdd(&h[b], 1);
    __syncthreads();
    for (int b2 = threadIdx.x; b2 < span; b2 += blockDim.x)
        g_hist[blockIdx.x * MAXSPAN + b2] = h[b2];
}

// ---------------- K5: exclusive prefix over partitions, per bin -----------
__global__ void k_prefix() {
    int span = min(g_dmax - g_dmin + 1, MAXSPAN);
    for (int b = threadIdx.x; b < span; b += blockDim.x) {
        int run = 0;
        for (int p = 0; p < NPART; p++) {
            int idx = p * MAXSPAN + b;
            int t = g_hist[idx];
            g_hist[idx] = run;
            run += t;
        }
    }
}

// ---------------- K6: base sum via prefix-histogram sweep -----------------
// Sum_{i<=j} log(1-p(deg_i,deg_j)+eps), no graph read at all.
__global__ void __launch_bounds__(256) k_base() {
    __shared__ int H[MAXSPAN];
    __shared__ double red[8];
    int dmin = g_dmin;
    int span = min(g_dmax - dmin + 1, MAXSPAN);
    for (int b = threadIdx.x; b < span; b += blockDim.x)
        H[b] = g_hist[blockIdx.x * MAXSPAN + b];
    __syncthreads();

    double acc = 0.0;
    int j0 = blockIdx.x * PSIZE;
    for (int jj = 0; jj < PSIZE; jj++) {
        int bj = min(max(g_deg[j0 + jj] - dmin, 0), span - 1);
        const float* Trow = g_Tbase + (size_t)bj * span;
        float part = 0.f;
        for (int b = threadIdx.x; b < span; b += blockDim.x)
            part += (float)H[b] * Trow[b];
        acc += (double)part;
        if (threadIdx.x == 0) acc += (double)Trow[bj];  // diagonal i==j
        __syncthreads();
        if (threadIdx.x == 0) H[bj]++;
        __syncthreads();
    }
#pragma unroll
    for (int o = 16; o; o >>= 1) acc += __shfl_down_sync(0xffffffffu, acc, o);
    if ((threadIdx.x & 31) == 0) red[threadIdx.x >> 5] = acc;
    __syncthreads();
    if (threadIdx.x == 0) {
        double t = 0.0;
        for (int w = 0; w < 8; w++) t += red[w];
        atomicAdd(&g_sum, t);
    }
}

// ---------------- K7: per-edge correction ----------------
__global__ void __launch_bounds__(256) k_edgesum() {
    int dmin = g_dmin;
    int span = min(g_dmax - dmin + 1, MAXSPAN);
    int ec = min(g_ecount, ECAP);
    double acc = 0.0;
    for (int e = blockIdx.x * blockDim.x + threadIdx.x; e < ec;
         e += gridDim.x * blockDim.x) {
        unsigned pk = g_edges[e];
        int i = (int)(pk >> 13), j = (int)(pk & 8191u);
        int bi = min(max(g_deg[i] - dmin, 0), span - 1);
        int bj = min(max(g_deg[j] - dmin, 0), span - 1);
        acc += (double)g_Tdiff[(size_t)bj * span + bi];
    }
#pragma unroll
    for (int o = 16; o; o >>= 1) acc += __shfl_down_sync(0xffffffffu, acc, o);
    __shared__ double red[8];
    if ((threadIdx.x & 31) == 0) red[threadIdx.x >> 5] = acc;
    __syncthreads();
    if (threadIdx.x == 0) {
        double t = 0.0;
        for (int w = 0; w < 8; w++) t += red[w];
        atomicAdd(&g_sum, t);
    }
}

// ---------------- K8: finalize ----------------
__global__ void k_final(float* out) { out[0] = -(float)g_sum; }

// ---------------- launch ----------------
extern "C" void kernel_launch(void* const* d_in, const int* in_sizes, int n_in,
                              void* d_out, int out_size) {
    const float* params = (const float*)d_in[0];  // [3]
    const float* graph  = (const float*)d_in[1];  // [8192*8192]
    float* out = (float*)d_out;

    k_init<<<1, 1>>>();
    k_deg_edges<<<NV, 256>>>(graph);          // the only big HBM pass (256 MB)
    k_minmax<<<NV / 256, 256>>>();
    k_fill<<<128, 256>>>(params);
    k_hist<<<NPART, PSIZE>>>();
    k_prefix<<<1, 256>>>();
    k_base<<<NPART, 256>>>();
    k_edgesum<<<256, 256>>>();
    k_final<<<1, 1>>>(out);
}

// round 3
// speedup vs baseline: 1.2097x; 1.2097x over previous
#include <cuda_runtime.h>
#include <cuda_bf16.h>

#define NV 8192
#define EPSV 1e-5f
#define MAXSPAN 2048
#define ECAP (1 << 22)     /* 4M edge slots, ~12x headroom over ~335K expected */
#define EBLK 192           /* edge-correction blocks inside k_baseedge */

// ---------------- device scratch (allocation-free contract) ----------------
__device__ int      g_deg[NV];
__device__ unsigned g_edges[ECAP];
__device__ int      g_ecount;
__device__ int      g_dmin, g_dmax;
__device__ double   g_sum;
__device__ float    g_Tbase[(size_t)MAXSPAN * MAXSPAN];  // log(1-p+eps)
__device__ float    g_Tdiff[(size_t)MAXSPAN * MAXSPAN];  // log(p+eps)-log(1-p+eps)

// ---------------- K0: reset state (degrees must be zeroed: atomics add in) --
__global__ void k_init() {
    int i = blockIdx.x * blockDim.x + threadIdx.x;
    g_deg[i] = 0;
    if (i == 0) { g_ecount = 0; g_sum = 0.0; }
}

// ---------------- K1: upper-triangle-only pass (~128MB instead of 256MB) ---
// Block = row i, reads only float4s covering columns j >= i (aligned down).
// Local count of nonzeros with j>=i feeds deg[i]; each edge j>i also
// scatter-atomicAdds deg[j] (mirror of the unread lower triangle).
// Edge indices compacted via block scan; ONE g_ecount atomic per block.
__global__ void __launch_bounds__(256) k_main(const float* __restrict__ g) {
    int row = blockIdx.x;
    const float4* rp = (const float4*)(g + (size_t)row * NV);
    int t0 = row >> 2;                       // first float4 index (aligned down)
    unsigned umask = 0;                      // 8 nibbles: nonzero pattern, j>=row only
#pragma unroll
    for (int k = 0; k < 8; k++) {
        int idx = t0 + threadIdx.x + (k << 8);
        if (idx < NV / 4) {
            float4 v = __ldg(&rp[idx]);
            int j0 = idx << 2;
            unsigned m = 0;
            if (v.x != 0.f && j0 + 0 >= row) m |= 1u;
            if (v.y != 0.f && j0 + 1 >= row) m |= 2u;
            if (v.z != 0.f && j0 + 2 >= row) m |= 4u;
            if (v.w != 0.f && j0 + 3 >= row) m |= 8u;
            umask |= m << (4 * k);
        }
    }
    int cnt = __popc(umask);
    int lane = threadIdx.x & 31, wid = threadIdx.x >> 5;

    // warp inclusive scan of counts
    int inc = cnt;
#pragma unroll
    for (int o = 1; o < 32; o <<= 1) {
        int nn = __shfl_up_sync(0xffffffffu, inc, o);
        if (lane >= o) inc += nn;
    }
    __shared__ int wsum[8], wbase[8], sbase;
    if (lane == 31) wsum[wid] = inc;
    __syncthreads();
    if (threadIdx.x == 0) {
        int run = 0;
        for (int w = 0; w < 8; w++) { wbase[w] = run; run += wsum[w]; }
        if (run) {
            atomicAdd(&g_deg[row], run);          // own-row upper contribution
            sbase = atomicAdd(&g_ecount, run);
        } else sbase = 0;
    }
    __syncthreads();

    int off = sbase + wbase[wid] + inc - cnt;
    unsigned m2 = umask;
    while (m2) {
        int b = __ffs(m2) - 1; m2 &= m2 - 1;
        int j = ((t0 + threadIdx.x + ((b >> 2) << 8)) << 2) + (b & 3);
        if (off < ECAP) g_edges[off] = ((unsigned)row << 13) | (unsigned)j;
        if (j > row) atomicAdd(&g_deg[j], 1);     // mirror lower-tri contribution
        off++;
    }
}

// ---------------- K2: fused degree min/max + table fill (single block) -----
__global__ void __launch_bounds__(1024) k_prep(const float* __restrict__ params) {
    __shared__ int smn[32], smx[32], sdmin, sspan;
    int tid = threadIdx.x;
    int mn = 0x7fffffff, mx = 0;
    for (int i = tid; i < NV; i += 1024) {
        int v = g_deg[i];
        mn = min(mn, v); mx = max(mx, v);
    }
#pragma unroll
    for (int o = 16; o; o >>= 1) {
        mn = min(mn, __shfl_down_sync(0xffffffffu, mn, o));
        mx = max(mx, __shfl_down_sync(0xffffffffu, mx, o));
    }
    if ((tid & 31) == 0) { smn[tid >> 5] = mn; smx[tid >> 5] = mx; }
    __syncthreads();
    if (tid == 0) {
        int a = smn[0], b = smx[0];
        for (int w = 1; w < 32; w++) { a = min(a, smn[w]); b = max(b, smx[w]); }
        g_dmin = a; g_dmax = b;
        sdmin = a; sspan = min(b - a + 1, MAXSPAN);
    }
    __syncthreads();

    float alpha = params[0], beta = params[1], sigma = params[2];
    int dmin = sdmin, span = sspan;
    long total = (long)span * span;
    for (long idx = tid; idx < total; idx += 1024) {
        int a = (int)(idx % span);   // i-side bin (alpha)
        int b = (int)(idx / span);   // j-side bin (beta)
        float s = alpha * (float)(dmin + a) + beta * (float)(dmin + b) + sigma;
        float p = 1.f / (1.f + expf(s));
        float l0 = logf(1.f - p + EPSV);
        g_Tbase[idx] = l0;
        g_Tdiff[idx] = logf(p + EPSV) - l0;
    }
}

// ---------------- K3: fused base sweep + per-edge correction ---------------
// Blocks 0..63:  base term. Block p builds its own prefix histogram
//                H[b] = #{i < 128p : bin_i = b} by scanning degrees (L2-hot),
//                then sweeps its 128 j's: acc += sum_b H[b]*Tbase[bj][b],
//                + diagonal, incrementing H as it goes.
// Blocks 64..:   edge correction sum of Tdiff over the compacted edge list.
__global__ void __launch_bounds__(256) k_baseedge() {
    __shared__ double red[8];
    int dmin = g_dmin;
    int span = min(g_dmax - dmin + 1, MAXSPAN);
    double acc = 0.0;

    if (blockIdx.x < 64) {
        __shared__ int H[MAXSPAN];
        int p = blockIdx.x;
        for (int b = threadIdx.x; b < span; b += blockDim.x) H[b] = 0;
        __syncthreads();
        for (int i = threadIdx.x; i < p * 128; i += blockDim.x) {
            int b = min(max(g_deg[i] - dmin, 0), span - 1);
            atomicAdd(&H[b], 1);
        }
        __syncthreads();

        int j0 = p * 128;
        for (int jj = 0; jj < 128; jj++) {
            int bj = min(max(g_deg[j0 + jj] - dmin, 0), span - 1);
            const float* Trow = g_Tbase + (size_t)bj * span;
            float part = 0.f;
            for (int b = threadIdx.x; b < span; b += blockDim.x)
                part += (float)H[b] * Trow[b];
            acc += (double)part;
            if (threadIdx.x == 0) acc += (double)Trow[bj];   // i == j diagonal
            __syncthreads();
            if (threadIdx.x == 0) H[bj]++;
            __syncthreads();
        }
    } else {
        int ec = min(g_ecount, ECAP);
        for (int e = (blockIdx.x - 64) * blockDim.x + threadIdx.x; e < ec;
             e += EBLK * blockDim.x) {
            unsigned pk = g_edges[e];
            int i = (int)(pk >> 13), j = (int)(pk & 8191u);
            int bi = min(max(g_deg[i] - dmin, 0), span - 1);
            int bj = min(max(g_deg[j] - dmin, 0), span - 1);
            acc += (double)g_Tdiff[(size_t)bj * span + bi];
        }
    }

#pragma unroll
    for (int o = 16; o; o >>= 1) acc += __shfl_down_sync(0xffffffffu, acc, o);
    if ((threadIdx.x & 31) == 0) red[threadIdx.x >> 5] = acc;
    __syncthreads();
    if (threadIdx.x == 0) {
        double t = 0.0;
        for (int w = 0; w < 8; w++) t += red[w];
        atomicAdd(&g_sum, t);
    }
}

// ---------------- K4: finalize ----------------
__global__ void k_final(float* out) { out[0] = -(float)g_sum; }

// ---------------- launch ----------------
extern "C" void kernel_launch(void* const* d_in, const int* in_sizes, int n_in,
                              void* d_out, int out_size) {
    const float* params = (const float*)d_in[0];  // [3]
    const float* graph  = (const float*)d_in[1];  // [8192*8192]
    float* out = (float*)d_out;

    k_init<<<NV / 256, 256>>>();
    k_main<<<NV, 256>>>(graph);       // ~128MB upper-triangle read
    k_prep<<<1, 1024>>>(params);      // minmax + table fill, one block
    k_baseedge<<<64 + EBLK, 256>>>(); // base sweep + edge correction
    k_final<<<1, 1>>>(out);
}

// round 4
// speedup vs baseline: 2.0806x; 1.7200x over previous
#include <cuda_runtime.h>
#include <cuda_bf16.h>

#define NV 8192
#define EPSV 1e-5f
#define MAXSPAN 2048
#define ECAP (1 << 22)     /* 4M edge slots, ~12x headroom over ~335K expected */
#define NPART 128          /* base-term partitions (blocks) */
#define PSIZE 64           /* NV / NPART */
#define NTRI (PSIZE * (PSIZE + 1) / 2)   /* 2080 intra-partition pairs */
#define EBLK 192           /* edge-correction blocks inside k_baseedge */

// ---------------- device scratch (allocation-free contract) ----------------
__device__ int      g_deg[NV];
__device__ unsigned g_edges[ECAP];
__device__ int      g_ecount;
__device__ int      g_dmin, g_dmax;
__device__ double   g_sum;
__device__ float    g_Tbase[(size_t)MAXSPAN * MAXSPAN];  // log(1-p+eps)
__device__ float    g_Tdiff[(size_t)MAXSPAN * MAXSPAN];  // log(p+eps)-log(1-p+eps)

// ---------------- K0: reset state (degrees must be zeroed: atomics add in) --
__global__ void k_init() {
    int i = blockIdx.x * blockDim.x + threadIdx.x;
    g_deg[i] = 0;
    if (i == 0) { g_ecount = 0; g_sum = 0.0; }
}

// ---------------- K1: upper-triangle-only pass (~128MB) --------------------
__global__ void __launch_bounds__(256) k_main(const float* __restrict__ g) {
    int row = blockIdx.x;
    const float4* rp = (const float4*)(g + (size_t)row * NV);
    int t0 = row >> 2;                       // first float4 index (aligned down)
    unsigned umask = 0;                      // 8 nibbles: nonzero pattern, j>=row only
#pragma unroll
    for (int k = 0; k < 8; k++) {
        int idx = t0 + threadIdx.x + (k << 8);
        if (idx < NV / 4) {
            float4 v = __ldg(&rp[idx]);
            int j0 = idx << 2;
            unsigned m = 0;
            if (v.x != 0.f && j0 + 0 >= row) m |= 1u;
            if (v.y != 0.f && j0 + 1 >= row) m |= 2u;
            if (v.z != 0.f && j0 + 2 >= row) m |= 4u;
            if (v.w != 0.f && j0 + 3 >= row) m |= 8u;
            umask |= m << (4 * k);
        }
    }
    int cnt = __popc(umask);
    int lane = threadIdx.x & 31, wid = threadIdx.x >> 5;

    int inc = cnt;
#pragma unroll
    for (int o = 1; o < 32; o <<= 1) {
        int nn = __shfl_up_sync(0xffffffffu, inc, o);
        if (lane >= o) inc += nn;
    }
    __shared__ int wsum[8], wbase[8], sbase;
    if (lane == 31) wsum[wid] = inc;
    __syncthreads();
    if (threadIdx.x == 0) {
        int run = 0;
        for (int w = 0; w < 8; w++) { wbase[w] = run; run += wsum[w]; }
        if (run) {
            atomicAdd(&g_deg[row], run);          // own-row upper contribution
            sbase = atomicAdd(&g_ecount, run);
        } else sbase = 0;
    }
    __syncthreads();

    int off = sbase + wbase[wid] + inc - cnt;
    unsigned m2 = umask;
    while (m2) {
        int b = __ffs(m2) - 1; m2 &= m2 - 1;
        int j = ((t0 + threadIdx.x + ((b >> 2) << 8)) << 2) + (b & 3);
        if (off < ECAP) g_edges[off] = ((unsigned)row << 13) | (unsigned)j;
        if (j > row) atomicAdd(&g_deg[j], 1);     // mirror lower-tri contribution
        off++;
    }
}

// ---------------- K2: fused degree min/max + table fill (single block) -----
__global__ void __launch_bounds__(1024) k_prep(const float* __restrict__ params) {
    __shared__ int smn[32], smx[32], sdmin, sspan;
    int tid = threadIdx.x;
    int mn = 0x7fffffff, mx = 0;
    for (int i = tid; i < NV; i += 1024) {
        int v = g_deg[i];
        mn = min(mn, v); mx = max(mx, v);
    }
#pragma unroll
    for (int o = 16; o; o >>= 1) {
        mn = min(mn, __shfl_down_sync(0xffffffffu, mn, o));
        mx = max(mx, __shfl_down_sync(0xffffffffu, mx, o));
    }
    if ((tid & 31) == 0) { smn[tid >> 5] = mn; smx[tid >> 5] = mx; }
    __syncthreads();
    if (tid == 0) {
        int a = smn[0], b = smx[0];
        for (int w = 1; w < 32; w++) { a = min(a, smn[w]); b = max(b, smx[w]); }
        g_dmin = a; g_dmax = b;
        sdmin = a; sspan = min(b - a + 1, MAXSPAN);
    }
    __syncthreads();

    float alpha = params[0], beta = params[1], sigma = params[2];
    int dmin = sdmin, span = sspan;
    long total = (long)span * span;
    for (long idx = tid; idx < total; idx += 1024) {
        int a = (int)(idx % span);   // i-side bin (alpha)
        int b = (int)(idx / span);   // j-side bin (beta)
        float s = alpha * (float)(dmin + a) + beta * (float)(dmin + b) + sigma;
        float p = 1.f / (1.f + expf(s));
        float l0 = logf(1.f - p + EPSV);
        g_Tbase[idx] = l0;
        g_Tdiff[idx] = logf(p + EPSV) - l0;
    }
}

// ---------------- K3: fully-parallel base term + per-edge correction -------
// Blocks 0..NPART-1 (base term, partition p = rows [64p, 64p+64)):
//   base_p = Σ_{j∈p} dot(H_p, Tbase[bj][·])        (H_p = hist of bins for i<64p)
//          + Σ_{ii<=jj within p} Tbase[b_jj][b_ii]  (triangle incl. diagonal)
//   Both sums are flat parallel loops — no sequential j sweep, no per-iter
//   barriers. Table (~span^2*4B ≈ 25KB) is L1-resident.
// Blocks NPART.. : edge correction over the compacted edge list.
__global__ void __launch_bounds__(256) k_baseedge() {
    __shared__ double red[8];
    int dmin = g_dmin;
    int span = min(g_dmax - dmin + 1, MAXSPAN);
    double acc = 0.0;

    if (blockIdx.x < NPART) {
        __shared__ int H[MAXSPAN];
        __shared__ int sbin[PSIZE];
        int p = blockIdx.x;
        for (int b = threadIdx.x; b < span; b += 256) H[b] = 0;
        __syncthreads();
        for (int i = threadIdx.x; i < p * PSIZE; i += 256) {
            int b = min(max(g_deg[i] - dmin, 0), span - 1);
            atomicAdd(&H[b], 1);
        }
        if (threadIdx.x < PSIZE)
            sbin[threadIdx.x] =
                min(max(g_deg[p * PSIZE + threadIdx.x] - dmin, 0), span - 1);
        __syncthreads();

        // cross term: (j, b) flat loop, PSIZE*span iterations
        int ncross = PSIZE * span;
        for (int idx = threadIdx.x; idx < ncross; idx += 256) {
            int jj = idx / span;
            int b  = idx - jj * span;
            acc += (double)((float)H[b] * g_Tbase[(size_t)sbin[jj] * span + b]);
        }
        // intra-partition triangle (ii <= jj), NTRI iterations
        for (int idx = threadIdx.x; idx < NTRI; idx += 256) {
            int jj = (int)((sqrtf(8.f * (float)idx + 1.f) - 1.f) * 0.5f);
            while ((jj + 1) * (jj + 2) / 2 <= idx) jj++;
            while (jj * (jj + 1) / 2 > idx) jj--;
            int ii = idx - jj * (jj + 1) / 2;
            acc += (double)g_Tbase[(size_t)sbin[jj] * span + sbin[ii]];
        }
    } else {
        int ec = min(g_ecount, ECAP);
        for (int e = (blockIdx.x - NPART) * 256 + threadIdx.x; e < ec;
             e += EBLK * 256) {
            unsigned pk = g_edges[e];
            int i = (int)(pk >> 13), j = (int)(pk & 8191u);
            int bi = min(max(g_deg[i] - dmin, 0), span - 1);
            int bj = min(max(g_deg[j] - dmin, 0), span - 1);
            acc += (double)g_Tdiff[(size_t)bj * span + bi];
        }
    }

#pragma unroll
    for (int o = 16; o; o >>= 1) acc += __shfl_down_sync(0xffffffffu, acc, o);
    if ((threadIdx.x & 31) == 0) red[threadIdx.x >> 5] = acc;
    __syncthreads();
    if (threadIdx.x == 0) {
        double t = 0.0;
        for (int w = 0; w < 8; w++) t += red[w];
        atomicAdd(&g_sum, t);
    }
}

// ---------------- K4: finalize ----------------
__global__ void k_final(float* out) { out[0] = -(float)g_sum; }

// ---------------- launch ----------------
extern "C" void kernel_launch(void* const* d_in, const int* in_sizes, int n_in,
                              void* d_out, int out_size) {
    const float* params = (const float*)d_in[0];  // [3]
    const float* graph  = (const float*)d_in[1];  // [8192*8192]
    float* out = (float*)d_out;

    k_init<<<NV / 256, 256>>>();
    k_main<<<NV, 256>>>(graph);            // ~128MB upper-triangle read
    k_prep<<<1, 1024>>>(params);           // minmax + table fill, one block
    k_baseedge<<<NPART + EBLK, 256>>>();   // parallel base + edge correction
    k_final<<<1, 1>>>(out);
}